// round 7
// baseline (speedup 1.0000x reference)
#include <cuda_runtime.h>
#include <cuda_fp16.h>
#include <cstdint>

// ---------------- Problem constants ----------------
#define BATCH   16
#define CIN     32
#define WH_IN   224
#define WH_OUT  222
#define COUT    64
#define KSTEPS  18
#define NTILES  (BATCH * WH_OUT * 2)     // 7104 = 148*48
#define TILES_PER_CTA 48
#define OPLANE  (BATCH * WH_OUT * WH_OUT)

// ---------------- SMEM layout ----------------
// A: ring of 4 y-row slots, each [16 chan-pairs][AST u32 cols] fp16x2.
// AST = 136: 136 % 32 == 8 -> A LDS banks 8q+r conflict-free; %4==0 -> STS.128 ok.
#define AST        136
#define SLOT_BYTES (16 * AST * 4)        // 8704
#define A_BYTES    (4 * SLOT_BYTES)      // 34816
#define SM_B       A_BYTES
// B row stride: 304 words == 16 (mod 32) -> LDS.128 phases conflict-free.
#define BSTR       1216
#define SMEM_BYTES (SM_B + COUT * BSTR)  // 112640

// ---------------- helpers ----------------
static __device__ __forceinline__ uint32_t smem_u32(const void* p) {
    uint32_t a;
    asm("{ .reg .u64 t; cvta.to.shared.u64 t, %1; cvt.u32.u64 %0, t; }" : "=r"(a) : "l"(p));
    return a;
}
static __device__ __forceinline__ uint32_t lds_u32(uint32_t a) {
    uint32_t v; asm volatile("ld.shared.b32 %0, [%1];" : "=r"(v) : "r"(a)); return v;
}
static __device__ __forceinline__ void lds_u128(uint32_t a, uint32_t* v) {
    asm volatile("ld.shared.v4.b32 {%0,%1,%2,%3}, [%4];"
                 : "=r"(v[0]), "=r"(v[1]), "=r"(v[2]), "=r"(v[3]) : "r"(a));
}
static __device__ __forceinline__ void sts_u128(uint32_t a, const uint32_t* v) {
    asm volatile("st.shared.v4.b32 [%0], {%1,%2,%3,%4};"
                 :: "r"(a), "r"(v[0]), "r"(v[1]), "r"(v[2]), "r"(v[3]));
}
// pack two f32 -> f16x2 word: LOW half = v0, HIGH half = v1
static __device__ __forceinline__ uint32_t pack_f16x2(float v0, float v1) {
    uint32_t w;
    asm("cvt.rn.f16x2.f32 %0, %1, %2;" : "=r"(w) : "f"(v1), "f"(v0));
    return w;
}
static __device__ __forceinline__ void mma_f16(float* d, const uint32_t* a,
                                               uint32_t b0, uint32_t b1) {
    asm volatile(
        "mma.sync.aligned.m16n8k16.row.col.f32.f16.f16.f32 "
        "{%0,%1,%2,%3}, {%4,%5,%6,%7}, {%8,%9}, {%0,%1,%2,%3};"
        : "+f"(d[0]), "+f"(d[1]), "+f"(d[2]), "+f"(d[3])
        : "r"(a[0]), "r"(a[1]), "r"(a[2]), "r"(a[3]), "r"(b0), "r"(b1));
}

// full[p] = bar 1+p (producer arrives, team p syncs)
// empty[p] = bar 3+p (team p arrives, producer syncs)
// rendezvous = bar 5 (all 384)
#define BAR_SYNC(id, n)   asm volatile("bar.sync %0, %1;"   :: "r"(id), "r"(n) : "memory")
#define BAR_ARRIVE(id, n) asm volatile("bar.arrive %0, %1;" :: "r"(id), "r"(n) : "memory")
#define MEMBAR_CTA()      asm volatile("membar.cta;" ::: "memory")

__global__ void __launch_bounds__(384, 1)
quanv_2t_kernel(const float* __restrict__ x, const float* __restrict__ w,
                float* __restrict__ out)
{
    extern __shared__ char smem[];
    const uint32_t sbase = smem_u32(smem);
    const uint32_t a_sm  = sbase;
    const uint32_t b_sm  = sbase + SM_B;

    const int tid = threadIdx.x;
    const int wid = tid >> 5;
    const int lid = tid & 31;
    const int t0  = blockIdx.x * TILES_PER_CTA;

    // ---- one-time: build B = w split into fp16 hi/lo, v4 slots ----
    #pragma unroll 1
    for (int u = tid; u < COUT * 72; u += 384) {
        const int n   = u / 72;
        const int rem = u - n * 72;
        const int ks  = rem >> 2;
        const int qq  = rem & 3;
        const int tap = ks % 9, ch = ks / 9;
        uint32_t bw[4];
        #pragma unroll
        for (int h = 0; h < 2; ++h) {
            const int c = 2 * (ch * 8 + qq + 4 * h);
            const float w0 = w[n * 288 + c * 9 + tap];
            const float w1 = w[n * 288 + (c + 1) * 9 + tap];
            const uint32_t hw = pack_f16x2(w0, w1);
            const float h0 = __half2float(__ushort_as_half((unsigned short)(hw & 0xFFFFu)));
            const float h1 = __half2float(__ushort_as_half((unsigned short)(hw >> 16)));
            bw[h]     = hw;
            bw[2 + h] = pack_f16x2(w0 - h0, w1 - h1);
        }
        sts_u128(b_sm + (uint32_t)(n * BSTR + rem * 16), bw);
    }
    __syncthreads();

    if (wid < 8) {
        // ======= CONSUMERS: 2 teams x 4 warps; warp = M32 x N64 =======
        const int team = wid >> 2;         // warps 0-3 team0, 4-7 team1
        const int wx   = wid & 3;          // M-quarter
        const int r = lid >> 2, q = lid & 3;
        const uint32_t bb = b_sm + (uint32_t)(r * BSTR + q * 16);

        uint32_t ab[2][2];
        #pragma unroll
        for (int j = 0; j < 2; ++j)
            #pragma unroll
            for (int h = 0; h < 2; ++h)
                ab[j][h] = a_sm + (uint32_t)(q * AST + wx * 32 + j * 16 + r + 8 * h) * 4;

        #pragma unroll 1
        for (int it = team; it < TILES_PER_CTA; it += 2) {
            const int t    = t0 + it;
            const int g    = t / WH_OUT;
            const int y    = t - g * WH_OUT;
            const int b    = g >> 1;
            const int half = g & 1;
            const int x0   = half ? 94 : 0;
            const int xoff = half ? 2 : 0;

            if ((y == 0 && it > 0) || (y == 1 && it > 1))
                BAR_SYNC(5, 384);                 // boundary rendezvous
            BAR_SYNC(1 + (it & 1), 256);          // rows staged

            uint32_t sl[3];
            #pragma unroll
            for (int d = 0; d < 3; ++d)
                sl[d] = (uint32_t)(((y + d) & 3) * SLOT_BYTES) + (uint32_t)(xoff * 4);

            float acc[2][8][4];
            #pragma unroll
            for (int j = 0; j < 2; ++j)
                #pragma unroll
                for (int nb = 0; nb < 8; ++nb)
                    #pragma unroll
                    for (int e = 0; e < 4; ++e) acc[j][nb][e] = 0.0f;

            #pragma unroll
            for (int ks = 0; ks < KSTEPS; ++ks) {
                const int tap = ks % 9, ch = ks / 9;
                const uint32_t off = sl[tap / 3] + (uint32_t)(ch * 8 * AST * 4 + (tap % 3) * 4);
                uint32_t ahi[2][4];
                #pragma unroll
                for (int j = 0; j < 2; ++j) {
                    ahi[j][0] = lds_u32(ab[j][0] + off);
                    ahi[j][1] = lds_u32(ab[j][1] + off);
                    ahi[j][2] = lds_u32(ab[j][0] + off + 4 * AST * 4);
                    ahi[j][3] = lds_u32(ab[j][1] + off + 4 * AST * 4);
                }
                #pragma unroll
                for (int nb = 0; nb < 8; ++nb) {
                    uint32_t bq[4];
                    lds_u128(bb + (uint32_t)(nb * 8 * BSTR + ks * 64), bq);
                    #pragma unroll
                    for (int j = 0; j < 2; ++j) {
                        mma_f16(acc[j][nb], ahi[j], bq[0], bq[1]);   // x * Wh
                        mma_f16(acc[j][nb], ahi[j], bq[2], bq[3]);   // x * Wl
                    }
                }
            }

            BAR_ARRIVE(3 + (it & 1), 256);        // smem reads done

            float* ob = out + ((size_t)b * WH_OUT + y) * WH_OUT
                            + (size_t)(2 * q) * OPLANE;
            #pragma unroll
            for (int j = 0; j < 2; ++j)
                #pragma unroll
                for (int h = 0; h < 2; ++h) {
                    const int px = x0 + wx * 32 + j * 16 + r + 8 * h;
                    #pragma unroll
                    for (int nb = 0; nb < 8; ++nb) {
                        ob[(size_t)(nb * 8) * OPLANE + px]     = acc[j][nb][2 * h];
                        ob[(size_t)(nb * 8 + 1) * OPLANE + px] = acc[j][nb][2 * h + 1];
                    }
                }
        }
    } else {
        // ======= PRODUCERS: 4 warps, rolling 1-row stage =======
        const int ptid = tid - 256;
        #pragma unroll 1
        for (int it = 0; it < TILES_PER_CTA; ++it) {
            const int t  = t0 + it;
            const int g  = t / WH_OUT;
            const int y  = t - g * WH_OUT;
            const int b  = g >> 1;
            const int xs = (g & 1) ? 92 : 0;

            if (it >= 2) BAR_SYNC(3 + (it & 1), 256);   // ring slot free
            if (y == 0 && it > 0) BAR_SYNC(5, 384);     // boundary rendezvous

            const int nrows = (it == 0 || y == 0) ? 3 : 1;
            const int yb    = (nrows == 3) ? y : (y + 2);

            #pragma unroll 1
            for (int u = ptid; u < nrows * 528; u += 128) {
                const int rrow = u / 528;
                const int v    = u - rrow * 528;
                const int c2   = v / 33;
                const int q4   = v - c2 * 33;
                const int yr   = yb + rrow;
                const float* gp = x + ((size_t)(b * CIN + 2 * c2) * WH_IN + yr) * WH_IN + xs + q4 * 4;
                const float4 f0 = *(const float4*)gp;
                const float4 f1 = *(const float4*)(gp + WH_IN * WH_IN);
                uint32_t hv[4];
                hv[0] = pack_f16x2(f0.x, f1.x);
                hv[1] = pack_f16x2(f0.y, f1.y);
                hv[2] = pack_f16x2(f0.z, f1.z);
                hv[3] = pack_f16x2(f0.w, f1.w);
                sts_u128(a_sm + (uint32_t)((yr & 3) * SLOT_BYTES)
                              + (uint32_t)((c2 * AST + q4 * 4) * 4), hv);
            }
            MEMBAR_CTA();
            BAR_ARRIVE(1 + (it & 1), 256);              // rows staged
        }
    }
}

extern "C" void kernel_launch(void* const* d_in, const int* in_sizes, int n_in,
                              void* d_out, int out_size)
{
    const float* x = (const float*)d_in[0];
    const float* w = (const float*)d_in[1];
    float* out = (float*)d_out;

    static bool attr_set = false;
    if (!attr_set) {
        cudaFuncSetAttribute(quanv_2t_kernel,
                             cudaFuncAttributeMaxDynamicSharedMemorySize, SMEM_BYTES);
        attr_set = true;
    }
    quanv_2t_kernel<<<148, 384, SMEM_BYTES>>>(x, w, out);
}

// round 9
// speedup vs baseline: 1.3580x; 1.3580x over previous
#include <cuda_runtime.h>
#include <cuda_fp16.h>
#include <cstdint>

// ---------------- Problem constants ----------------
#define BATCH   16
#define CIN     32
#define WH_IN   224
#define WH_OUT  222
#define COUT    64
#define KSTEPS  18
#define NTILES  (BATCH * WH_OUT * 2)     // 7104 = 148*48
#define TILES_PER_CTA 48
#define OPLANE  (BATCH * WH_OUT * WH_OUT)

// ---------------- SMEM layout ----------------
// A: ring of 6 y-row slots, each [16 chan-pairs][AST u32 cols] fp16x2.
// AST = 136: 136 % 32 == 8 -> A LDS banks 8q+r conflict-free; %4==0 -> STS.128 ok.
#define AST        136
#define SLOT_BYTES (16 * AST * 4)        // 8704
#define NSLOTS     6
#define A_BYTES    (NSLOTS * SLOT_BYTES) // 52224
#define SM_B       A_BYTES
// B row stride: 304 words == 16 (mod 32) -> LDS.128 phases conflict-free.
#define BSTR       1216
#define SMEM_BYTES (SM_B + COUT * BSTR)  // 130048

// Barrier ids: full[it&3] = 1..4 (256), empty[it&3] = 5..8 (256), rendezvous = 9 (384)
#define BAR_SYNC(id, n)   asm volatile("bar.sync %0, %1;"   :: "r"(id), "r"(n) : "memory")
#define BAR_ARRIVE(id, n) asm volatile("bar.arrive %0, %1;" :: "r"(id), "r"(n) : "memory")
#define MEMBAR_CTA()      asm volatile("membar.cta;" ::: "memory")

// ---------------- helpers ----------------
static __device__ __forceinline__ uint32_t smem_u32(const void* p) {
    uint32_t a;
    asm("{ .reg .u64 t; cvta.to.shared.u64 t, %1; cvt.u32.u64 %0, t; }" : "=r"(a) : "l"(p));
    return a;
}
static __device__ __forceinline__ uint32_t lds_u32(uint32_t a) {
    uint32_t v; asm volatile("ld.shared.b32 %0, [%1];" : "=r"(v) : "r"(a)); return v;
}
static __device__ __forceinline__ void lds_u128(uint32_t a, uint32_t* v) {
    asm volatile("ld.shared.v4.b32 {%0,%1,%2,%3}, [%4];"
                 : "=r"(v[0]), "=r"(v[1]), "=r"(v[2]), "=r"(v[3]) : "r"(a));
}
static __device__ __forceinline__ void sts_u128(uint32_t a, const uint32_t* v) {
    asm volatile("st.shared.v4.b32 [%0], {%1,%2,%3,%4};"
                 :: "r"(a), "r"(v[0]), "r"(v[1]), "r"(v[2]), "r"(v[3]));
}
// pack two f32 -> f16x2 word: LOW half = v0, HIGH half = v1
static __device__ __forceinline__ uint32_t pack_f16x2(float v0, float v1) {
    uint32_t w;
    asm("cvt.rn.f16x2.f32 %0, %1, %2;" : "=r"(w) : "f"(v1), "f"(v0));
    return w;
}
static __device__ __forceinline__ void mma_f16(float* d, const uint32_t* a,
                                               uint32_t b0, uint32_t b1) {
    asm volatile(
        "mma.sync.aligned.m16n8k16.row.col.f32.f16.f16.f32 "
        "{%0,%1,%2,%3}, {%4,%5,%6,%7}, {%8,%9}, {%0,%1,%2,%3};"
        : "+f"(d[0]), "+f"(d[1]), "+f"(d[2]), "+f"(d[3])
        : "r"(a[0]), "r"(a[1]), "r"(a[2]), "r"(a[3]), "r"(b0), "r"(b1));
}

// Stage one input row (16 chan-pairs x 132 cols) into its ring slot.
// All global loads issued first (MLP ~10), then convert + STS.
static __device__ __forceinline__ void stage_row(const float* __restrict__ x,
                                                 int b, int xs, int yr,
                                                 uint32_t a_sm, int ptid) {
    const uint32_t slot = a_sm + (uint32_t)((yr % NSLOTS) * SLOT_BYTES);
    float4 f0[5], f1[5];
    #pragma unroll
    for (int i = 0; i < 5; ++i) {
        const int u = ptid + i * 128;
        if (u < 528) {
            const int c2 = u / 33;
            const int q4 = u - c2 * 33;
            const float* gp = x + ((size_t)(b * CIN + 2 * c2) * WH_IN + yr) * WH_IN
                                + xs + q4 * 4;
            f0[i] = *(const float4*)gp;
            f1[i] = *(const float4*)(gp + WH_IN * WH_IN);
        }
    }
    #pragma unroll
    for (int i = 0; i < 5; ++i) {
        const int u = ptid + i * 128;
        if (u < 528) {
            const int c2 = u / 33;
            const int q4 = u - c2 * 33;
            uint32_t hv[4];
            hv[0] = pack_f16x2(f0[i].x, f1[i].x);
            hv[1] = pack_f16x2(f0[i].y, f1[i].y);
            hv[2] = pack_f16x2(f0[i].z, f1[i].z);
            hv[3] = pack_f16x2(f0[i].w, f1[i].w);
            sts_u128(slot + (uint32_t)((c2 * AST + q4 * 4) * 4), hv);
        }
    }
}

__global__ void __launch_bounds__(384, 1)
quanv_r6b_kernel(const float* __restrict__ x, const float* __restrict__ w,
                 float* __restrict__ out)
{
    extern __shared__ char smem[];
    const uint32_t sbase = smem_u32(smem);
    const uint32_t a_sm  = sbase;
    const uint32_t b_sm  = sbase + SM_B;

    const int tid = threadIdx.x;
    const int wid = tid >> 5;
    const int lid = tid & 31;
    const int t0  = blockIdx.x * TILES_PER_CTA;

    // ---- one-time: build B = w split into fp16 hi/lo, v4 slots ----
    #pragma unroll 1
    for (int u = tid; u < COUT * 72; u += 384) {
        const int n   = u / 72;
        const int rem = u - n * 72;
        const int ks  = rem >> 2;
        const int qq  = rem & 3;
        const int tap = ks % 9, ch = ks / 9;
        uint32_t bw[4];
        #pragma unroll
        for (int h = 0; h < 2; ++h) {
            const int c = 2 * (ch * 8 + qq + 4 * h);
            const float w0 = w[n * 288 + c * 9 + tap];
            const float w1 = w[n * 288 + (c + 1) * 9 + tap];
            const uint32_t hw = pack_f16x2(w0, w1);
            const float h0 = __half2float(__ushort_as_half((unsigned short)(hw & 0xFFFFu)));
            const float h1 = __half2float(__ushort_as_half((unsigned short)(hw >> 16)));
            bw[h]     = hw;
            bw[2 + h] = pack_f16x2(w0 - h0, w1 - h1);
        }
        sts_u128(b_sm + (uint32_t)(n * BSTR + rem * 16), bw);
    }
    __syncthreads();

    if (wid < 8) {
        // ======= CONSUMERS: 2 teams x 4 warps; warp = M32 x N64 =======
        const int team = wid >> 2;
        const int wx   = wid & 3;
        const int r = lid >> 2, q = lid & 3;
        const uint32_t bb = b_sm + (uint32_t)(r * BSTR + q * 16);

        uint32_t ab[2][2];
        #pragma unroll
        for (int j = 0; j < 2; ++j)
            #pragma unroll
            for (int h = 0; h < 2; ++h)
                ab[j][h] = a_sm + (uint32_t)(q * AST + wx * 32 + j * 16 + r + 8 * h) * 4;

        #pragma unroll 1
        for (int it = team; it < TILES_PER_CTA; it += 2) {
            const int t    = t0 + it;
            const int g    = t / WH_OUT;
            const int y    = t - g * WH_OUT;
            const int b    = g >> 1;
            const int half = g & 1;
            const int x0   = half ? 94 : 0;
            const int xoff = half ? 2 : 0;

            if ((y == 0 && it > 0) || (y == 1 && it > 1))
                BAR_SYNC(9, 384);                 // boundary rendezvous
            BAR_SYNC(1 + (it & 3), 256);          // rows staged for tile it

            uint32_t sl[3];
            #pragma unroll
            for (int d = 0; d < 3; ++d)
                sl[d] = (uint32_t)(((y + d) % NSLOTS) * SLOT_BYTES) + (uint32_t)(xoff * 4);

            float acc[2][8][4];
            #pragma unroll
            for (int j = 0; j < 2; ++j)
                #pragma unroll
                for (int nb = 0; nb < 8; ++nb)
                    #pragma unroll
                    for (int e = 0; e < 4; ++e) acc[j][nb][e] = 0.0f;

            #pragma unroll
            for (int ks = 0; ks < KSTEPS; ++ks) {
                const int tap = ks % 9, ch = ks / 9;
                const uint32_t off = sl[tap / 3] + (uint32_t)(ch * 8 * AST * 4 + (tap % 3) * 4);
                uint32_t ahi[2][4];
                #pragma unroll
                for (int j = 0; j < 2; ++j) {
                    ahi[j][0] = lds_u32(ab[j][0] + off);
                    ahi[j][1] = lds_u32(ab[j][1] + off);
                    ahi[j][2] = lds_u32(ab[j][0] + off + 4 * AST * 4);
                    ahi[j][3] = lds_u32(ab[j][1] + off + 4 * AST * 4);
                }
                #pragma unroll
                for (int nb = 0; nb < 8; ++nb) {
                    uint32_t bq[4];
                    lds_u128(bb + (uint32_t)(nb * 8 * BSTR + ks * 64), bq);
                    #pragma unroll
                    for (int j = 0; j < 2; ++j) {
                        mma_f16(acc[j][nb], ahi[j], bq[0], bq[1]);   // x * Wh
                        mma_f16(acc[j][nb], ahi[j], bq[2], bq[3]);   // x * Wl
                    }
                }
            }

            BAR_ARRIVE(5 + (it & 3), 256);        // smem reads done (ring class)

            float* ob = out + ((size_t)b * WH_OUT + y) * WH_OUT
                            + (size_t)(2 * q) * OPLANE;
            #pragma unroll
            for (int j = 0; j < 2; ++j)
                #pragma unroll
                for (int h = 0; h < 2; ++h) {
                    const int px = x0 + wx * 32 + j * 16 + r + 8 * h;
                    #pragma unroll
                    for (int nb = 0; nb < 8; ++nb) {
                        ob[(size_t)(nb * 8) * OPLANE + px]     = acc[j][nb][2 * h];
                        ob[(size_t)(nb * 8 + 1) * OPLANE + px] = acc[j][nb][2 * h + 1];
                    }
                }
        }
    } else {
        // ======= PRODUCERS: 4 warps, rolling 1-row stage, 4-deep lead =======
        const int ptid = tid - 256;
        #pragma unroll 1
        for (int it = 0; it < TILES_PER_CTA; ++it) {
            const int t  = t0 + it;
            const int g  = t / WH_OUT;
            const int y  = t - g * WH_OUT;
            const int b  = g >> 1;
            const int xs = (g & 1) ? 92 : 0;

            if (y == 0 && it > 0) BAR_SYNC(9, 384);       // boundary rendezvous
            if (it >= 4) BAR_SYNC(5 + (it & 3), 256);     // ring slot free (tile it-4 done)

            if (it == 0 || y == 0) {
                stage_row(x, b, xs, y + 0, a_sm, ptid);
                stage_row(x, b, xs, y + 1, a_sm, ptid);
                stage_row(x, b, xs, y + 2, a_sm, ptid);
            } else {
                stage_row(x, b, xs, y + 2, a_sm, ptid);
            }
            MEMBAR_CTA();
            BAR_ARRIVE(1 + (it & 3), 256);                // rows staged for tile it
        }
    }
}

extern "C" void kernel_launch(void* const* d_in, const int* in_sizes, int n_in,
                              void* d_out, int out_size)
{
    const float* x = (const float*)d_in[0];
    const float* w = (const float*)d_in[1];
    float* out = (float*)d_out;

    static bool attr_set = false;
    if (!attr_set) {
        cudaFuncSetAttribute(quanv_r6b_kernel,
                             cudaFuncAttributeMaxDynamicSharedMemorySize, SMEM_BYTES);
        attr_set = true;
    }
    quanv_r6b_kernel<<<148, 384, SMEM_BYTES>>>(x, w, out);
}

// round 10
// speedup vs baseline: 1.6126x; 1.1875x over previous
#include <cuda_runtime.h>
#include <cuda_fp16.h>
#include <cstdint>

// ---------------- Problem constants ----------------
#define BATCH   16
#define CIN     32
#define WH_IN   224
#define WH_OUT  222
#define COUT    64
#define KSTEPS  18
#define NTILES  (BATCH * WH_OUT * 2)     // 7104 = 148*48
#define TILES_PER_CTA 48
#define OPLANE  (BATCH * WH_OUT * WH_OUT)

// ---------------- SMEM layout ----------------
// A: ring of 6 y-row slots, each [16 chan-pairs][AST u32 cols] fp16x2.
// AST = 136: 136 % 32 == 8 -> A LDS banks 8q+r conflict-free; %4==0 -> STS.128 ok.
#define AST        136
#define SLOT_BYTES (16 * AST * 4)        // 8704
#define NSLOTS     6
#define A_BYTES    (NSLOTS * SLOT_BYTES) // 52224
#define SM_B       A_BYTES
// B row: 72 v2-slots (8B) = 576B used; stride 672B -> 168 words == 8 (mod 32):
// per 16-lane LDS.64 phase, words r*8 + 2q + {0,1} = 0..31 all distinct.
#define BSTR       672
#define SMEM_BYTES (SM_B + COUT * BSTR)  // 52224 + 43008 = 95232

// Barrier ids: full[it&3] = 1..4 (256), empty[it&3] = 5..8 (256), rendezvous = 9 (384)
#define BAR_SYNC(id, n)   asm volatile("bar.sync %0, %1;"   :: "r"(id), "r"(n) : "memory")
#define BAR_ARRIVE(id, n) asm volatile("bar.arrive %0, %1;" :: "r"(id), "r"(n) : "memory")
#define MEMBAR_CTA()      asm volatile("membar.cta;" ::: "memory")

// ---------------- helpers ----------------
static __device__ __forceinline__ uint32_t smem_u32(const void* p) {
    uint32_t a;
    asm("{ .reg .u64 t; cvta.to.shared.u64 t, %1; cvt.u32.u64 %0, t; }" : "=r"(a) : "l"(p));
    return a;
}
static __device__ __forceinline__ uint32_t lds_u32(uint32_t a) {
    uint32_t v; asm volatile("ld.shared.b32 %0, [%1];" : "=r"(v) : "r"(a)); return v;
}
static __device__ __forceinline__ void lds_u64(uint32_t a, uint32_t* v) {
    asm volatile("ld.shared.v2.b32 {%0,%1}, [%2];" : "=r"(v[0]), "=r"(v[1]) : "r"(a));
}
static __device__ __forceinline__ void sts_u64(uint32_t a, const uint32_t* v) {
    asm volatile("st.shared.v2.b32 [%0], {%1,%2};" :: "r"(a), "r"(v[0]), "r"(v[1]));
}
static __device__ __forceinline__ void sts_u128(uint32_t a, const uint32_t* v) {
    asm volatile("st.shared.v4.b32 [%0], {%1,%2,%3,%4};"
                 :: "r"(a), "r"(v[0]), "r"(v[1]), "r"(v[2]), "r"(v[3]));
}
// pack two f32 -> f16x2 word: LOW half = v0, HIGH half = v1
static __device__ __forceinline__ uint32_t pack_f16x2(float v0, float v1) {
    uint32_t w;
    asm("cvt.rn.f16x2.f32 %0, %1, %2;" : "=r"(w) : "f"(v1), "f"(v0));
    return w;
}
static __device__ __forceinline__ void mma_f16(float* d, const uint32_t* a,
                                               uint32_t b0, uint32_t b1) {
    asm volatile(
        "mma.sync.aligned.m16n8k16.row.col.f32.f16.f16.f32 "
        "{%0,%1,%2,%3}, {%4,%5,%6,%7}, {%8,%9}, {%0,%1,%2,%3};"
        : "+f"(d[0]), "+f"(d[1]), "+f"(d[2]), "+f"(d[3])
        : "r"(a[0]), "r"(a[1]), "r"(a[2]), "r"(a[3]), "r"(b0), "r"(b1));
}

// Stage one input row (16 chan-pairs x 132 cols) into its ring slot.
// All global loads issued first (MLP ~10), then convert + STS.
static __device__ __forceinline__ void stage_row(const float* __restrict__ x,
                                                 int b, int xs, int yr,
                                                 uint32_t a_sm, int ptid) {
    const uint32_t slot = a_sm + (uint32_t)((yr % NSLOTS) * SLOT_BYTES);
    float4 f0[5], f1[5];
    #pragma unroll
    for (int i = 0; i < 5; ++i) {
        const int u = ptid + i * 128;
        if (u < 528) {
            const int c2 = u / 33;
            const int q4 = u - c2 * 33;
            const float* gp = x + ((size_t)(b * CIN + 2 * c2) * WH_IN + yr) * WH_IN
                                + xs + q4 * 4;
            f0[i] = *(const float4*)gp;
            f1[i] = *(const float4*)(gp + WH_IN * WH_IN);
        }
    }
    #pragma unroll
    for (int i = 0; i < 5; ++i) {
        const int u = ptid + i * 128;
        if (u < 528) {
            const int c2 = u / 33;
            const int q4 = u - c2 * 33;
            uint32_t hv[4];
            hv[0] = pack_f16x2(f0[i].x, f1[i].x);
            hv[1] = pack_f16x2(f0[i].y, f1[i].y);
            hv[2] = pack_f16x2(f0[i].z, f1[i].z);
            hv[3] = pack_f16x2(f0[i].w, f1[i].w);
            sts_u128(slot + (uint32_t)((c2 * AST + q4 * 4) * 4), hv);
        }
    }
}

__global__ void __launch_bounds__(384, 1)
quanv_1p_kernel(const float* __restrict__ x, const float* __restrict__ w,
                float* __restrict__ out)
{
    extern __shared__ char smem[];
    const uint32_t sbase = smem_u32(smem);
    const uint32_t a_sm  = sbase;
    const uint32_t b_sm  = sbase + SM_B;

    const int tid = threadIdx.x;
    const int wid = tid >> 5;
    const int lid = tid & 31;
    const int t0  = blockIdx.x * TILES_PER_CTA;

    // ---- one-time: build B = fp16(w), v2 slots {bh(h0), bh(h1)} ----
    #pragma unroll 1
    for (int u = tid; u < COUT * 72; u += 384) {
        const int n   = u / 72;
        const int rem = u - n * 72;
        const int ks  = rem >> 2;
        const int qq  = rem & 3;
        const int tap = ks % 9, ch = ks / 9;
        uint32_t bw[2];
        #pragma unroll
        for (int h = 0; h < 2; ++h) {
            const int c = 2 * (ch * 8 + qq + 4 * h);
            bw[h] = pack_f16x2(w[n * 288 + c * 9 + tap], w[n * 288 + (c + 1) * 9 + tap]);
        }
        sts_u64(b_sm + (uint32_t)(n * BSTR + rem * 8), bw);
    }
    __syncthreads();

    if (wid < 8) {
        // ======= CONSUMERS: 2 teams x 4 warps; warp = M32 x N64 =======
        const int team = wid >> 2;
        const int wx   = wid & 3;
        const int r = lid >> 2, q = lid & 3;
        const uint32_t bb = b_sm + (uint32_t)(r * BSTR + q * 8);

        uint32_t ab[2][2];
        #pragma unroll
        for (int j = 0; j < 2; ++j)
            #pragma unroll
            for (int h = 0; h < 2; ++h)
                ab[j][h] = a_sm + (uint32_t)(q * AST + wx * 32 + j * 16 + r + 8 * h) * 4;

        #pragma unroll 1
        for (int it = team; it < TILES_PER_CTA; it += 2) {
            const int t    = t0 + it;
            const int g    = t / WH_OUT;
            const int y    = t - g * WH_OUT;
            const int b    = g >> 1;
            const int half = g & 1;
            const int x0   = half ? 94 : 0;
            const int xoff = half ? 2 : 0;

            if ((y == 0 && it > 0) || (y == 1 && it > 1))
                BAR_SYNC(9, 384);                 // boundary rendezvous
            BAR_SYNC(1 + (it & 3), 256);          // rows staged for tile it

            uint32_t sl[3];
            #pragma unroll
            for (int d = 0; d < 3; ++d)
                sl[d] = (uint32_t)(((y + d) % NSLOTS) * SLOT_BYTES) + (uint32_t)(xoff * 4);

            float acc[2][8][4];
            #pragma unroll
            for (int j = 0; j < 2; ++j)
                #pragma unroll
                for (int nb = 0; nb < 8; ++nb)
                    #pragma unroll
                    for (int e = 0; e < 4; ++e) acc[j][nb][e] = 0.0f;

            #pragma unroll
            for (int ks = 0; ks < KSTEPS; ++ks) {
                const int tap = ks % 9, ch = ks / 9;
                const uint32_t off = sl[tap / 3] + (uint32_t)(ch * 8 * AST * 4 + (tap % 3) * 4);
                uint32_t ahi[2][4];
                #pragma unroll
                for (int j = 0; j < 2; ++j) {
                    ahi[j][0] = lds_u32(ab[j][0] + off);
                    ahi[j][1] = lds_u32(ab[j][1] + off);
                    ahi[j][2] = lds_u32(ab[j][0] + off + 4 * AST * 4);
                    ahi[j][3] = lds_u32(ab[j][1] + off + 4 * AST * 4);
                }
                #pragma unroll
                for (int nb = 0; nb < 8; ++nb) {
                    uint32_t bq[2];
                    lds_u64(bb + (uint32_t)(nb * 8 * BSTR + ks * 32), bq);
                    #pragma unroll
                    for (int j = 0; j < 2; ++j)
                        mma_f16(acc[j][nb], ahi[j], bq[0], bq[1]);   // x * fp16(W)
                }
            }

            BAR_ARRIVE(5 + (it & 3), 256);        // smem reads done (ring class)

            float* ob = out + ((size_t)b * WH_OUT + y) * WH_OUT
                            + (size_t)(2 * q) * OPLANE;
            #pragma unroll
            for (int j = 0; j < 2; ++j)
                #pragma unroll
                for (int h = 0; h < 2; ++h) {
                    const int px = x0 + wx * 32 + j * 16 + r + 8 * h;
                    #pragma unroll
                    for (int nb = 0; nb < 8; ++nb) {
                        ob[(size_t)(nb * 8) * OPLANE + px]     = acc[j][nb][2 * h];
                        ob[(size_t)(nb * 8 + 1) * OPLANE + px] = acc[j][nb][2 * h + 1];
                    }
                }
        }
    } else {
        // ======= PRODUCERS: 4 warps, rolling 1-row stage, 4-deep lead =======
        const int ptid = tid - 256;
        #pragma unroll 1
        for (int it = 0; it < TILES_PER_CTA; ++it) {
            const int t  = t0 + it;
            const int g  = t / WH_OUT;
            const int y  = t - g * WH_OUT;
            const int b  = g >> 1;
            const int xs = (g & 1) ? 92 : 0;

            if (y == 0 && it > 0) BAR_SYNC(9, 384);       // boundary rendezvous
            if (it >= 4) BAR_SYNC(5 + (it & 3), 256);     // ring slot free (tile it-4 done)

            if (it == 0 || y == 0) {
                stage_row(x, b, xs, y + 0, a_sm, ptid);
                stage_row(x, b, xs, y + 1, a_sm, ptid);
                stage_row(x, b, xs, y + 2, a_sm, ptid);
            } else {
                stage_row(x, b, xs, y + 2, a_sm, ptid);
            }
            MEMBAR_CTA();
            BAR_ARRIVE(1 + (it & 3), 256);                // rows staged for tile it
        }
    }
}

extern "C" void kernel_launch(void* const* d_in, const int* in_sizes, int n_in,
                              void* d_out, int out_size)
{
    const float* x = (const float*)d_in[0];
    const float* w = (const float*)d_in[1];
    float* out = (float*)d_out;

    static bool attr_set = false;
    if (!attr_set) {
        cudaFuncSetAttribute(quanv_1p_kernel,
                             cudaFuncAttributeMaxDynamicSharedMemorySize, SMEM_BYTES);
        attr_set = true;
    }
    quanv_1p_kernel<<<148, 384, SMEM_BYTES>>>(x, w, out);
}